// round 3
// baseline (speedup 1.0000x reference)
#include <cuda_runtime.h>
#include <math.h>

#define GDIM 128
#define G3 (GDIM*GDIM*GDIM)
#define NPART 4096
#define NBIN 64            // bins of width 2 on grid axis 0
#define HCAP 160           // per-warp hit-list capacity

// Sorted particle data (scratch; __device__ globals, no allocation)
__device__ float4 g_ps[NPART * 2];     // [2p]=(gp0,gp1,gp2,omega) [2p+1]=(em0..3)
__device__ int    g_pcs[NPART + 32];   // packed floor cell, +32 pad sentinels
__device__ int    g_binstart[NBIN + 1];

// ---------------------------------------------------------------------------
// Fused prep + deterministic counting sort by bin = c0>>1.
// Single block, 1024 threads = 32 warps; warp w owns particles [128w,128w+128)
// in 4 chunks of 32. Per-warp running bin counters give the stable local rank;
// cross-warp prefix is only 32 deep.
// ---------------------------------------------------------------------------
__global__ void __launch_bounds__(1024)
sort_kernel(const float* __restrict__ pos,
            const float* __restrict__ inten,
            const float* __restrict__ emo) {
    __shared__ int cnt[32][NBIN];     // per-warp bin counts -> exclusive prefixes
    __shared__ int bstart[NBIN + 1];
    const int tid  = threadIdx.x;
    const int w    = tid >> 5;
    const int lane = tid & 31;
    const unsigned FULL = 0xffffffffu;
    const unsigned lmlt = (1u << lane) - 1u;

    for (int i = tid; i < 32 * NBIN; i += 1024) ((int*)cnt)[i] = 0;
    __syncthreads();

    int    mypc[4], mybin[4], myrank[4];
    float4 mypA[4], mypE[4];
#pragma unroll
    for (int k = 0; k < 4; k++) {
        const int i = w * 128 + k * 32 + lane;
        const float gp0 = (pos[3*i+0] + 1.0f) * 63.5f;
        const float gp1 = (pos[3*i+1] + 1.0f) * 63.5f;
        const float gp2 = (pos[3*i+2] + 1.0f) * 63.5f;
        const int c0 = min(max((int)floorf(gp0), 0), GDIM-1);
        const int c1 = min(max((int)floorf(gp1), 0), GDIM-1);
        const int c2 = min(max((int)floorf(gp2), 0), GDIM-1);
        mypc[k] = c0 | (c1 << 8) | (c2 << 16);
        const int b = c0 >> 1;
        const unsigned m = __match_any_sync(FULL, b);
        const int r = __popc(m & lmlt);
        mybin[k]  = b;
        myrank[k] = cnt[w][b] + r;     // running count + rank in chunk
        __syncwarp();
        if (r == 0) cnt[w][b] += __popc(m);
        __syncwarp();
        mypA[k] = make_float4(gp0, gp1, gp2, inten[i] * 0.01f);
        mypE[k] = make_float4(emo[4*i+0], emo[4*i+1], emo[4*i+2], emo[4*i+3]);
    }
    __syncthreads();

    // Exclusive prefix over the 32 warps for each bin (thread t owns bin t).
    if (tid < NBIN) {
        int s = 0;
#pragma unroll
        for (int wi = 0; wi < 32; wi++) { const int v = cnt[wi][tid]; cnt[wi][tid] = s; s += v; }
        bstart[tid] = s;   // bin totals (temporarily)
    }
    __syncthreads();
    if (tid == 0) {
        int s = 0;
#pragma unroll
        for (int b = 0; b < NBIN; b++) { const int t = bstart[b]; bstart[b] = s; s += t; }
        bstart[NBIN] = s;
    }
    __syncthreads();

#pragma unroll
    for (int k = 0; k < 4; k++) {
        const int p = bstart[mybin[k]] + cnt[w][mybin[k]] + myrank[k];
        g_pcs[p]      = mypc[k];
        g_ps[2*p + 0] = mypA[k];
        g_ps[2*p + 1] = mypE[k];
    }
    if (tid <= NBIN) g_binstart[tid] = bstart[tid];
    if (tid < 32)    g_pcs[NPART + tid] = 0x0000FF00;   // c1=255: fails every window
}

// ---------------------------------------------------------------------------
// One warp per sample. Each lane owns ONE of the 32 cells actually needed:
// 8 trilinear corners (block coords in {1,2}^3) + their 24 face neighbors.
// Hits are compacted into a per-warp smem list, then processed in a counted
// ILP-friendly loop (no shfl / ffs serial chain).
// ---------------------------------------------------------------------------
__global__ void __launch_bounds__(256)
main_kernel(const float* __restrict__ spos,
            const float* __restrict__ H0,
            const float* __restrict__ E0,
            float* __restrict__ out) {
    __shared__ float sv[8][5][64];
    __shared__ int   hl[8][HCAP];
    const unsigned FULL = 0xffffffffu;
    const int wib  = threadIdx.x >> 5;
    const int lane = threadIdx.x & 31;
    const unsigned lmlt = (1u << lane) - 1u;
    const int s    = (blockIdx.x << 3) + wib;

    const float px = spos[3*s+0];
    const float py = spos[3*s+1];
    const float pz = spos[3*s+2];
    // grid axis0 <- comp2, axis1 <- comp1, axis2 <- comp0 (reference transpose)
    const float t0 = fminf(fmaxf((pz + 1.0f) * 63.5f, 0.0f), 127.0f);
    const float t1 = fminf(fmaxf((py + 1.0f) * 63.5f, 0.0f), 127.0f);
    const float t2 = fminf(fmaxf((px + 1.0f) * 63.5f, 0.0f), 127.0f);
    const int i0 = (int)floorf(t0); const float f0 = t0 - (float)i0;
    const int i1 = (int)floorf(t1); const float f1 = t1 - (float)i1;
    const int i2 = (int)floorf(t2); const float f2 = t2 - (float)i2;

    // lane -> block coords (b0,b1,b2), covering the 32 needed cells
    int b0, b1, b2;
    if (lane < 8) {
        b0 = 1 + ((lane >> 2) & 1); b1 = 1 + ((lane >> 1) & 1); b2 = 1 + (lane & 1);
    } else {
        const int idx = lane - 8, axis = idx >> 3, rest = idx & 7;
        const int s3 = ((rest >> 2) & 1) * 3;
        const int u = 1 + ((rest >> 1) & 1), v = 1 + (rest & 1);
        b0 = (axis == 0) ? s3 : u;
        b1 = (axis == 1) ? s3 : ((axis == 0) ? u : v);
        b2 = (axis == 2) ? s3 : v;
    }
    const int gc0 = min(max(i0 - 1 + b0, 0), 127);
    const int gc1 = min(max(i1 - 1 + b1, 0), 127);
    const int gc2 = min(max(i2 - 1 + b2, 0), 127);
    const float gcf0 = (float)gc0, gcf1 = (float)gc1, gcf2 = (float)gc2;

    // particle-window (covers all 32 cells)
    const int lo0 = min(max(i0 - 1, 0), 127) - 9, hi0 = min(max(i0 + 2, 0), 127) + 9;
    const int lo1 = min(max(i1 - 1, 0), 127) - 9, hi1 = min(max(i1 + 2, 0), 127) + 9;
    const int lo2 = min(max(i2 - 1, 0), 127) - 9, hi2 = min(max(i2 + 2, 0), 127) + 9;
    const unsigned sp0 = (unsigned)(hi0 - lo0);
    const unsigned sp1 = (unsigned)(hi1 - lo1);
    const unsigned sp2 = (unsigned)(hi2 - lo2);

    // contiguous candidate segment from the c0-sorted order
    const int binlo = max(lo0, 0) >> 1;
    const int binhi = min(hi0, 127) >> 1;
    const int j0 = g_binstart[binlo];
    const int j1 = g_binstart[binhi + 1];

    float aH = 0.f, aE0 = 0.f, aE1 = 0.f, aE2 = 0.f, aE3 = 0.f;

    // per-hit body: |gc - floor(gp)| <= 9 on each axis (particle floor cells
    // never need clamping: positions are strictly interior), Gaussian of the
    // true (unclamped-cell) distance, accumulate 5 channels.
    auto body = [&](int idx) {
        const float4 A  = __ldg(&g_ps[2*idx + 0]);
        const float4 Em = __ldg(&g_ps[2*idx + 1]);
        const bool in = (fabsf(gcf0 - floorf(A.x)) <= 9.0f) &
                        (fabsf(gcf1 - floorf(A.y)) <= 9.0f) &
                        (fabsf(gcf2 - floorf(A.z)) <= 9.0f);
        const float d0 = gcf0 - A.x;
        const float d1 = gcf1 - A.y;
        const float d2 = gcf2 - A.z;
        const float ssum = fmaf(d0, d0, fmaf(d1, d1, d2 * d2));
        const float e = __expf(ssum * -0.048828125f);
        float wv = in ? A.w : 0.0f;
        wv *= e;
        aH  += wv;
        aE0 += wv * Em.x;  aE1 += wv * Em.y;
        aE2 += wv * Em.z;  aE3 += wv * Em.w;
    };

    int nh = 0;
    for (int base = j0 & ~31; base < j1; base += 32) {
        const int pcv = g_pcs[base + lane];
        const int c0 = pcv & 255, c1 = (pcv >> 8) & 255, c2 = (pcv >> 16) & 255;
        const bool hit = ((unsigned)(c0 - lo0) <= sp0) &
                         ((unsigned)(c1 - lo1) <= sp1) &
                         ((unsigned)(c2 - lo2) <= sp2);
        const unsigned msk = __ballot_sync(FULL, hit);
        if (hit) hl[wib][nh + __popc(msk & lmlt)] = base + lane;
        nh += __popc(msk);
        if (nh >= HCAP - 32) {           // uniform across warp
            int k = 0;
            for (; k + 2 <= nh; k += 2) { body(hl[wib][k]); body(hl[wib][k+1]); }
            if (k < nh) body(hl[wib][k]);
            nh = 0;
        }
    }
    {
        int k = 0;
        for (; k + 2 <= nh; k += 2) { body(hl[wib][k]); body(hl[wib][k+1]); }
        if (k < nh) body(hl[wib][k]);
    }

    // add base grid values, stash in shared (only the 32 needed slots)
    const int ci   = b0 * 16 + b1 * 4 + b2;
    const int flat = (gc0 * GDIM + gc1) * GDIM + gc2;
    sv[wib][0][ci] = aH  + __ldg(&H0[flat]);
    sv[wib][1][ci] = aE0 + __ldg(&E0[0*G3 + flat]);
    sv[wib][2][ci] = aE1 + __ldg(&E0[1*G3 + flat]);
    sv[wib][3][ci] = aE2 + __ldg(&E0[2*G3 + flat]);
    sv[wib][4][ci] = aE3 + __ldg(&E0[3*G3 + flat]);
    __syncwarp();

    // diffusion step + ReLU + trilinear reduce (8 corner lanes)
#pragma unroll
    for (int ch = 0; ch < 5; ch++) {
        float part = 0.0f;
        if (lane < 8) {
            const int d0 = (lane >> 2) & 1, d1c = (lane >> 1) & 1, d2c = lane & 1;
            const int cc = (1 + d0) * 16 + (1 + d1c) * 4 + (1 + d2c);
            const float* v = sv[wib][ch];
            const float c = v[cc];
            const float lap = v[cc-16] + v[cc+16] + v[cc-4] + v[cc+4]
                            + v[cc-1]  + v[cc+1]  - 6.0f * c;
            float val;
            if (ch == 0) val = c * (1.0f - 5e-5f) + 0.002f * lap;
            else         val = c * (1.0f - 5e-5f) + 5e-5f + 0.001f * lap;
            val = fmaxf(val, 0.0f);
            const float wq = (d0  ? f0 : 1.0f - f0)
                           * (d1c ? f1 : 1.0f - f1)
                           * (d2c ? f2 : 1.0f - f2);
            part = val * wq;
        }
        part += __shfl_down_sync(FULL, part, 4);
        part += __shfl_down_sync(FULL, part, 2);
        part += __shfl_down_sync(FULL, part, 1);
        if (lane == 0) out[s * 5 + ch] = part;
    }
}

extern "C" void kernel_launch(void* const* d_in, const int* in_sizes, int n_in,
                              void* d_out, int out_size) {
    const float* positions   = (const float*)d_in[0];  // (4096,3)
    const float* intensities = (const float*)d_in[1];  // (4096,)
    const float* emotions    = (const float*)d_in[2];  // (4096,4)
    const float* sample_pos  = (const float*)d_in[3];  // (8,1024,3)
    const float* H0          = (const float*)d_in[4];  // (128,128,128)
    const float* E0          = (const float*)d_in[5];  // (4,128,128,128)
    float* out = (float*)d_out;                        // (8,1024,5)

    sort_kernel<<<1, 1024>>>(positions, intensities, emotions);
    main_kernel<<<1024, 256>>>(sample_pos, H0, E0, out);
    (void)in_sizes; (void)n_in; (void)out_size;
}